// round 1
// baseline (speedup 1.0000x reference)
#include <cuda_runtime.h>
#include <math.h>

// Problem constants (fixed shapes for this dataset)
#define NMAX   200000
#define DDIM   128
#define DROW   129          // memory / message row length (D+1)
#define LAMB   30.0f
#define OUTC   30.0f
#define SLOPE  0.01f
#define EPSC   1e-10f

// GEMM tiling
#define BM 64               // rows per CTA
#define BK 32               // K chunk
#define TM 4                // rows per thread
#define TN 8                // cols per thread
#define NTHREADS 256        // 16 x 16 thread grid

#define FEAT_LD 260         // feat smem row stride (floats)
#define H1_LD   132         // h1 smem row stride (floats)

// node -> edge index map (-1 if no update). Rebuilt every launch (deterministic).
__device__ int g_map[NMAX];

__global__ void init_map_kernel(int n) {
    int i = blockIdx.x * blockDim.x + threadIdx.x;
    if (i < n) g_map[i] = -1;
}

__global__ void scatter_map_kernel(const int* __restrict__ srcs, int e) {
    int i = blockIdx.x * blockDim.x + threadIdx.x;
    if (i < e) g_map[srcs[i]] = i;
}

__device__ __forceinline__ float leaky(float x) {
    return x >= 0.0f ? x : SLOPE * x;
}

__global__ __launch_bounds__(NTHREADS, 2)
void ctdg_main_kernel(
    const float* __restrict__ memory,      // N x 129
    const float* __restrict__ last_update, // N
    const float* __restrict__ msgs,        // E x 129
    const float* __restrict__ ts,          // E
    const float* __restrict__ static_emb,  // N x 128
    const float* __restrict__ W1,          // 256 x 128
    const float* __restrict__ b1,          // 128
    const float* __restrict__ W2,          // 128 x 128
    const float* __restrict__ b2,          // 128
    const float* __restrict__ e_lamb_p,    // 1
    const float* __restrict__ now_p,       // 1
    float* __restrict__ out,               // N x 128
    int n)
{
    extern __shared__ float smem[];
    float* feats = smem;                   // BM x FEAT_LD  (reused as h1: BM x H1_LD)
    float* ws    = smem + BM * FEAT_LD;    // BK x 128

    __shared__ float s_decay[BM];
    __shared__ float s_a[BM];              // 1/(cnt+eps)
    __shared__ float s_dsc[BM];            // exp((lu-now)/OUTPUT)
    __shared__ int   s_e[BM];

    const int tid = threadIdx.x;
    const int ty  = tid >> 4;              // 0..15
    const int tx  = tid & 15;              // 0..15
    const int row0 = blockIdx.x * BM;

    const float now = now_p[0];
    const float el  = e_lamb_p[0];

    // -------- per-row parameters --------
    if (tid < BM) {
        int node = row0 + tid;
        float dec = 1.0f, lu = 0.0f, cnt = 1.0f;
        int e = -1;
        if (node < n) {
            e = g_map[node];
            if (e >= 0) {
                lu  = ts[e];
                dec = expf((last_update[node] - lu) * (1.0f / LAMB));
                cnt = memory[(long)node * DROW + DDIM] * dec + msgs[(long)e * DROW + DDIM];
            } else {
                lu  = last_update[node];
                cnt = memory[(long)node * DROW + DDIM];
            }
        }
        s_decay[tid] = dec;
        s_e[tid]     = e;
        s_a[tid]     = 1.0f / (cnt + EPSC);
        s_dsc[tid]   = expf((lu - now) * (1.0f / OUTC));
    }
    __syncthreads();

    // -------- build feat tile: feats[r][k] = a*msum, feats[r][128+k] = msum --------
    for (int idx = tid; idx < BM * DDIM; idx += NTHREADS) {
        int r = idx >> 7;        // /128
        int k = idx & 127;
        int node = row0 + r;
        float v = 0.0f;
        if (node < n) {
            v = memory[(long)node * DROW + k] * s_decay[r];
            int e = s_e[r];
            if (e >= 0) v += msgs[(long)e * DROW + k];
        }
        feats[r * FEAT_LD + k]        = s_a[r] * v;
        feats[r * FEAT_LD + DDIM + k] = v;
    }

    // -------- GEMM1: h1 = leaky(feat @ W1 + b1), K = 256 --------
    float acc[TM][TN];
    #pragma unroll
    for (int i = 0; i < TM; i++)
        #pragma unroll
        for (int j = 0; j < TN; j++) acc[i][j] = 0.0f;

    for (int kb = 0; kb < 2 * DDIM; kb += BK) {
        __syncthreads();  // prior chunk reads done (also covers feat writes on first iter)
        // load W1 chunk rows [kb, kb+32): 32x128 floats = 1024 float4 / 256 threads
        {
            const float4* src = (const float4*)(W1 + kb * DDIM);
            float4* dst = (float4*)ws;
            #pragma unroll
            for (int t = 0; t < 4; t++) dst[tid + t * NTHREADS] = src[tid + t * NTHREADS];
        }
        __syncthreads();
        #pragma unroll
        for (int kk = 0; kk < BK; kk++) {
            float a[TM];
            #pragma unroll
            for (int i = 0; i < TM; i++)
                a[i] = feats[(ty * TM + i) * FEAT_LD + kb + kk];
            float4 b0 = *(const float4*)(ws + kk * DDIM + tx * TN);
            float4 b4 = *(const float4*)(ws + kk * DDIM + tx * TN + 4);
            float b[TN] = {b0.x, b0.y, b0.z, b0.w, b4.x, b4.y, b4.z, b4.w};
            #pragma unroll
            for (int i = 0; i < TM; i++)
                #pragma unroll
                for (int j = 0; j < TN; j++)
                    acc[i][j] = fmaf(a[i], b[j], acc[i][j]);
        }
    }

    __syncthreads();  // everyone done reading feats; safe to overwrite as h1

    {
        float4 bb0 = *(const float4*)(b1 + tx * TN);
        float4 bb4 = *(const float4*)(b1 + tx * TN + 4);
        float bb[TN] = {bb0.x, bb0.y, bb0.z, bb0.w, bb4.x, bb4.y, bb4.z, bb4.w};
        #pragma unroll
        for (int i = 0; i < TM; i++) {
            float v[TN];
            #pragma unroll
            for (int j = 0; j < TN; j++) v[j] = leaky(acc[i][j] + bb[j]);
            float* dst = feats + (ty * TM + i) * H1_LD + tx * TN;
            *(float4*)(dst)     = make_float4(v[0], v[1], v[2], v[3]);
            *(float4*)(dst + 4) = make_float4(v[4], v[5], v[6], v[7]);
        }
    }

    // -------- GEMM2: h = leaky(h1 @ W2 + b2), K = 128 --------
    #pragma unroll
    for (int i = 0; i < TM; i++)
        #pragma unroll
        for (int j = 0; j < TN; j++) acc[i][j] = 0.0f;

    for (int kb = 0; kb < DDIM; kb += BK) {
        __syncthreads();
        {
            const float4* src = (const float4*)(W2 + kb * DDIM);
            float4* dst = (float4*)ws;
            #pragma unroll
            for (int t = 0; t < 4; t++) dst[tid + t * NTHREADS] = src[tid + t * NTHREADS];
        }
        __syncthreads();
        #pragma unroll
        for (int kk = 0; kk < BK; kk++) {
            float a[TM];
            #pragma unroll
            for (int i = 0; i < TM; i++)
                a[i] = feats[(ty * TM + i) * H1_LD + kb + kk];
            float4 b0 = *(const float4*)(ws + kk * DDIM + tx * TN);
            float4 b4 = *(const float4*)(ws + kk * DDIM + tx * TN + 4);
            float b[TN] = {b0.x, b0.y, b0.z, b0.w, b4.x, b4.y, b4.z, b4.w};
            #pragma unroll
            for (int i = 0; i < TM; i++)
                #pragma unroll
                for (int j = 0; j < TN; j++)
                    acc[i][j] = fmaf(a[i], b[j], acc[i][j]);
        }
    }

    // -------- epilogue: dec, blend with static_emb --------
    {
        float4 bb0 = *(const float4*)(b2 + tx * TN);
        float4 bb4 = *(const float4*)(b2 + tx * TN + 4);
        float bb[TN] = {bb0.x, bb0.y, bb0.z, bb0.w, bb4.x, bb4.y, bb4.z, bb4.w};
        const float oml = 1.0f - el;
        #pragma unroll
        for (int i = 0; i < TM; i++) {
            int r = ty * TM + i;
            int node = row0 + r;
            if (node >= n) continue;
            float dsc = s_dsc[r];
            const float* se = static_emb + (long)node * DDIM + tx * TN;
            float4 s0 = *(const float4*)(se);
            float4 s4 = *(const float4*)(se + 4);
            float s[TN] = {s0.x, s0.y, s0.z, s0.w, s4.x, s4.y, s4.z, s4.w};
            float o[TN];
            #pragma unroll
            for (int j = 0; j < TN; j++) {
                float h = leaky(acc[i][j] + bb[j]);
                o[j] = el * s[j] + oml * (h * dsc);
            }
            float* dst = out + (long)node * DDIM + tx * TN;
            *(float4*)(dst)     = make_float4(o[0], o[1], o[2], o[3]);
            *(float4*)(dst + 4) = make_float4(o[4], o[5], o[6], o[7]);
        }
    }
}

extern "C" void kernel_launch(void* const* d_in, const int* in_sizes, int n_in,
                              void* d_out, int out_size) {
    const float* memory      = (const float*)d_in[0];
    const float* last_update = (const float*)d_in[1];
    const float* msgs        = (const float*)d_in[2];
    const float* ts          = (const float*)d_in[3];
    const float* static_emb  = (const float*)d_in[4];
    const float* W1          = (const float*)d_in[5];
    const float* b1          = (const float*)d_in[6];
    const float* W2          = (const float*)d_in[7];
    const float* b2          = (const float*)d_in[8];
    const float* e_lamb      = (const float*)d_in[9];
    const float* now_time    = (const float*)d_in[10];
    const int*   srcs        = (const int*)d_in[11];
    float* out = (float*)d_out;

    const int n = in_sizes[1];   // last_update: N
    const int e = in_sizes[3];   // unique_timestamps: E

    init_map_kernel<<<(n + 255) / 256, 256>>>(n);
    scatter_map_kernel<<<(e + 255) / 256, 256>>>(srcs, e);

    size_t smem_bytes = (size_t)(BM * FEAT_LD + BK * DDIM) * sizeof(float); // ~83 KB
    cudaFuncSetAttribute(ctdg_main_kernel,
                         cudaFuncAttributeMaxDynamicSharedMemorySize,
                         (int)smem_bytes);
    int grid = (n + BM - 1) / BM;
    ctdg_main_kernel<<<grid, NTHREADS, smem_bytes>>>(
        memory, last_update, msgs, ts, static_emb,
        W1, b1, W2, b2, e_lamb, now_time, out, n);
}

// round 4
// speedup vs baseline: 2.5374x; 2.5374x over previous
#include <cuda_runtime.h>
#include <cuda_bf16.h>
#include <math.h>
#include <stdint.h>

#define NMAX   200000
#define DDIM   128
#define LAMB   30.0f
#define OUTC   30.0f
#define SLOPE  0.01f
#define EPSC   1e-10f

#define TILE_M 128
#define NTHR   256

// smem layout (bytes, dynamic):
//  A_hi: 128 rows x 136 bf16 (pitch 272B = 17*16) = 34816 ; A_lo at +34816
//  B buf0 at 69632 (hi), lo at +36864 ; B buf1 at 143360 (hi), lo at +36864
#define A_PITCH_B  272
#define B_PITCH_B  144
#define A_LO_OFF   34816u
#define B_SPLIT    36864u
#define BBUF0_OFF  69632u
#define BBUF1_OFF  143360u
#define SMEM_BYTES 217088

// packed transposed/split weights in global
// W1T: 2 k-chunks x [256 n][72 k] ; W2T: 2 x [128 n][72 k]
__device__ int g_map[NMAX];
__device__ __align__(16) __nv_bfloat16 g_W1T_hi[2 * 256 * 72];
__device__ __align__(16) __nv_bfloat16 g_W1T_lo[2 * 256 * 72];
__device__ __align__(16) __nv_bfloat16 g_W2T_hi[2 * 128 * 72];
__device__ __align__(16) __nv_bfloat16 g_W2T_lo[2 * 128 * 72];

// ---------------- helpers ----------------
__device__ __forceinline__ uint32_t smem_u32(const void* p) {
    uint32_t a;
    asm("{ .reg .u64 t; cvta.to.shared.u64 t, %1; cvt.u32.u64 %0, t; }" : "=r"(a) : "l"(p));
    return a;
}
__device__ __forceinline__ void sts32(uint32_t a, uint32_t v) {
    asm volatile("st.shared.b32 [%0], %1;" :: "r"(a), "r"(v) : "memory");
}
__device__ __forceinline__ void sts128(uint32_t a, uint32_t x, uint32_t y, uint32_t z, uint32_t w) {
    asm volatile("st.shared.v4.b32 [%0], {%1,%2,%3,%4};" :: "r"(a), "r"(x), "r"(y), "r"(z), "r"(w) : "memory");
}
__device__ __forceinline__ void ldsm4(uint32_t& r0, uint32_t& r1, uint32_t& r2, uint32_t& r3, uint32_t addr) {
    asm volatile("ldmatrix.sync.aligned.m8n8.x4.shared.b16 {%0,%1,%2,%3}, [%4];"
                 : "=r"(r0), "=r"(r1), "=r"(r2), "=r"(r3) : "r"(addr) : "memory");
}
__device__ __forceinline__ void cp16(uint32_t dst, const void* src) {
    asm volatile("cp.async.cg.shared.global [%0], [%1], 16;" :: "r"(dst), "l"(src) : "memory");
}
#define CP_COMMIT() asm volatile("cp.async.commit_group;" ::: "memory")
#define CP_WAIT(N)  asm volatile("cp.async.wait_group %0;" :: "n"(N) : "memory")

__device__ __forceinline__ void mma16816(float* d,
    uint32_t a0, uint32_t a1, uint32_t a2, uint32_t a3, uint32_t b0, uint32_t b1) {
    asm volatile(
        "mma.sync.aligned.m16n8k16.row.col.f32.bf16.bf16.f32 "
        "{%0,%1,%2,%3}, {%4,%5,%6,%7}, {%8,%9}, {%0,%1,%2,%3};"
        : "+f"(d[0]), "+f"(d[1]), "+f"(d[2]), "+f"(d[3])
        : "r"(a0), "r"(a1), "r"(a2), "r"(a3), "r"(b0), "r"(b1));
}

__device__ __forceinline__ float leaky(float x) { return x >= 0.0f ? x : SLOPE * x; }

__device__ __forceinline__ void split2(float x0, float x1, uint32_t& hi, uint32_t& lo) {
    __nv_bfloat16 h0 = __float2bfloat16(x0), h1 = __float2bfloat16(x1);
    __nv_bfloat16 l0 = __float2bfloat16(x0 - __bfloat162float(h0));
    __nv_bfloat16 l1 = __float2bfloat16(x1 - __bfloat162float(h1));
    hi = (uint32_t)__bfloat16_as_ushort(h0) | ((uint32_t)__bfloat16_as_ushort(h1) << 16);
    lo = (uint32_t)__bfloat16_as_ushort(l0) | ((uint32_t)__bfloat16_as_ushort(l1) << 16);
}

__device__ __forceinline__ void split_store8(uint32_t ahi, uint32_t alo, const float* v) {
    uint32_t hw[4], lw[4];
#pragma unroll
    for (int p = 0; p < 4; p++) split2(v[2 * p], v[2 * p + 1], hw[p], lw[p]);
    sts128(ahi, hw[0], hw[1], hw[2], hw[3]);
    sts128(alo, lw[0], lw[1], lw[2], lw[3]);
}

__device__ __forceinline__ void cp_tile(uint32_t dst, const __nv_bfloat16* src, int bytes, int tid) {
    const char* s = (const char*)src;
    for (int off = tid * 16; off < bytes; off += NTHR * 16)
        cp16(dst + (uint32_t)off, s + off);
}

// ---------------- prep kernels ----------------
__global__ void prep_kernel(const float* __restrict__ W1, const float* __restrict__ W2, int n) {
    int i = blockIdx.x * blockDim.x + threadIdx.x;
    if (i < n) g_map[i] = -1;
    if (i < 256 * 128) {   // W1T[n][k]: n<128 -> W1[k][n]; n>=128 -> W1[128+k][n-128]
        int nn = i >> 7, k = i & 127;
        float v = (nn < 128) ? W1[k * DDIM + nn] : W1[(128 + k) * DDIM + (nn - 128)];
        __nv_bfloat16 hi = __float2bfloat16(v);
        __nv_bfloat16 lo = __float2bfloat16(v - __bfloat162float(hi));
        int off = (k >> 6) * (256 * 72) + nn * 72 + (k & 63);
        g_W1T_hi[off] = hi; g_W1T_lo[off] = lo;
    }
    if (i < 128 * 128) {   // W2T[n][k] = W2[k][n]
        int nn = i >> 7, k = i & 127;
        float v = W2[k * DDIM + nn];
        __nv_bfloat16 hi = __float2bfloat16(v);
        __nv_bfloat16 lo = __float2bfloat16(v - __bfloat162float(hi));
        int off = (k >> 6) * (128 * 72) + nn * 72 + (k & 63);
        g_W2T_hi[off] = hi; g_W2T_lo[off] = lo;
    }
}
__global__ void scatter_kernel(const int* __restrict__ srcs, int e) {
    int i = blockIdx.x * blockDim.x + threadIdx.x;
    if (i < e) g_map[srcs[i]] = i;
}

// ---------------- GEMM chunk (K=64) via ldmatrix ----------------
// acc[m*NT + t][4]. NT=16: tiles 8..15 use B rows +128 (Q half).
// lane: lq = lane>>2 (groupID), lr = lane&3.
template<int NT>
__device__ __forceinline__ void gemm_chunk(float (&acc)[2 * NT][4],
    uint32_t Ahi, uint32_t Bhi, int warp_m, int warp_n, int lane)
{
    const int l8 = lane & 7;
    const int q  = lane >> 3;          // quad index 0..3
#pragma unroll
    for (int ks = 0; ks < 4; ks++) {
        const uint32_t koff = (uint32_t)ks * 32u;
        // ---- A fragments: per (m, hi/lo) one ldmatrix.x4 ----
        // quad q: row = base + (q&1)*8 + l8 ; col-bytes = (q>>1)*16
        uint32_t ah[2][4], al[2][4];
#pragma unroll
        for (int m = 0; m < 2; m++) {
            uint32_t rowa = (uint32_t)(warp_m * 32 + m * 16 + (q & 1) * 8 + l8);
            uint32_t aoff = rowa * A_PITCH_B + koff + (uint32_t)(q >> 1) * 16u;
            ldsm4(ah[m][0], ah[m][1], ah[m][2], ah[m][3], Ahi + aoff);
            ldsm4(al[m][0], al[m][1], al[m][2], al[m][3], Ahi + A_LO_OFF + aoff);
        }
        // ---- B fragments + MMAs per tile: one ldmatrix.x4 gives bh0,bh1,bl0,bl1 ----
#pragma unroll
        for (int t = 0; t < NT; t++) {
            int nrow0 = warp_n * 64 + (t & 7) * 8 + ((NT == 16 && t >= 8) ? 128 : 0);
            // quads: q0 hi k0-7, q1 hi k8-15, q2 lo k0-7, q3 lo k8-15
            uint32_t boff = (uint32_t)(nrow0 + l8) * B_PITCH_B + koff + (uint32_t)(q & 1) * 16u
                          + ((q >> 1) ? B_SPLIT : 0u);
            uint32_t bh0, bh1, bl0, bl1;
            ldsm4(bh0, bh1, bl0, bl1, Bhi + boff);
#pragma unroll
            for (int m = 0; m < 2; m++) {
                mma16816(acc[m * NT + t], ah[m][0], ah[m][1], ah[m][2], ah[m][3], bh0, bh1);
                mma16816(acc[m * NT + t], ah[m][0], ah[m][1], ah[m][2], ah[m][3], bl0, bl1);
                mma16816(acc[m * NT + t], al[m][0], al[m][1], al[m][2], al[m][3], bh0, bh1);
            }
        }
    }
}

// ---------------- main kernel ----------------
__global__ __launch_bounds__(NTHR, 1)
void ctdg_hmma_kernel(
    const float* __restrict__ memory,
    const float* __restrict__ last_update,
    const float* __restrict__ msgs,
    const float* __restrict__ ts,
    const float* __restrict__ static_emb,
    const float* __restrict__ b1,
    const float* __restrict__ b2,
    const float* __restrict__ e_lamb_p,
    const float* __restrict__ now_p,
    float* __restrict__ out,
    int n)
{
    extern __shared__ char dsm[];
    __shared__ float s_dec[TILE_M], s_a[TILE_M], s_dsc[TILE_M];
    __shared__ int   s_e[TILE_M];

    const int tid = threadIdx.x;
    const int wid = tid >> 5;
    const int lane = tid & 31;
    const int lq = lane >> 2, lr = lane & 3;
    const int warp_m = wid & 3, warp_n = wid >> 2;
    const int row0 = blockIdx.x * TILE_M;

    const uint32_t smA  = smem_u32(dsm);
    const uint32_t smB0 = smA + BBUF0_OFF;
    const uint32_t smB1 = smA + BBUF1_OFF;

    // stage W1 chunks (async)
    cp_tile(smB0,           g_W1T_hi,            36864, tid);
    cp_tile(smB0 + B_SPLIT, g_W1T_lo,            36864, tid);
    CP_COMMIT();
    cp_tile(smB1,           g_W1T_hi + 256 * 72, 36864, tid);
    cp_tile(smB1 + B_SPLIT, g_W1T_lo + 256 * 72, 36864, tid);
    CP_COMMIT();

    const float now = __ldg(now_p);
    const float el  = __ldg(e_lamb_p);

    // per-row params
    if (tid < TILE_M) {
        int node = row0 + tid;
        float dec = 1.0f, lu = 0.0f, cnt = 1.0f;
        int e = -1;
        if (node < n) {
            e = g_map[node];
            float lun = last_update[node];
            float cm  = memory[(long)node * (DDIM + 1) + DDIM];
            if (e >= 0) {
                lu  = ts[e];
                dec = expf((lun - lu) * (1.0f / LAMB));
                cnt = cm * dec + msgs[(long)e * (DDIM + 1) + DDIM];
            } else { lu = lun; cnt = cm; }
        }
        s_dec[tid] = dec; s_e[tid] = e;
        s_a[tid]   = 1.0f / (cnt + EPSC);
        s_dsc[tid] = expf((lu - now) * (1.0f / OUTC));
    }
    __syncthreads();

    // build V = mem*dec + msg (128x128), split hi/lo into A buffers
    for (int g = tid; g < TILE_M * 16; g += NTHR) {
        int r = g >> 4, k0 = (g & 15) * 8;
        int node = row0 + r;
        float v[8];
        if (node < n) {
            float dec = s_dec[r];
            int e = s_e[r];
            const float* mrow = memory + (long)node * (DDIM + 1) + k0;
#pragma unroll
            for (int j = 0; j < 8; j++) v[j] = mrow[j] * dec;
            if (e >= 0) {
                const float* gm = msgs + (long)e * (DDIM + 1) + k0;
#pragma unroll
                for (int j = 0; j < 8; j++) v[j] += gm[j];
            }
        } else {
#pragma unroll
            for (int j = 0; j < 8; j++) v[j] = 0.0f;
        }
        uint32_t soff = (uint32_t)r * A_PITCH_B + (uint32_t)k0 * 2;
        split_store8(smA + soff, smA + A_LO_OFF + soff, v);
    }

    // -------- GEMM1: D1(128x256) = V @ W1T, 3-term split --------
    float acc1[32][4];
#pragma unroll
    for (int i = 0; i < 32; i++)
#pragma unroll
        for (int j = 0; j < 4; j++) acc1[i][j] = 0.0f;

    CP_WAIT(1); __syncthreads();                 // W1 chunk0 + V ready
    gemm_chunk<16>(acc1, smA, smB0, warp_m, warp_n, lane);
    CP_WAIT(0); __syncthreads();                 // W1 chunk1 ready, buf0 free
    cp_tile(smB0,           g_W2T_hi, 18432, tid);
    cp_tile(smB0 + B_SPLIT, g_W2T_lo, 18432, tid);
    CP_COMMIT();
    gemm_chunk<16>(acc1, smA + 128u, smB1, warp_m, warp_n, lane);
    __syncthreads();                             // all GEMM1 done: V, buf1 free
    cp_tile(smB1,           g_W2T_hi + 128 * 72, 18432, tid);
    cp_tile(smB1 + B_SPLIT, g_W2T_lo + 128 * 72, 18432, tid);
    CP_COMMIT();

    // -------- mid epilogue: H = leaky(a*P + Q + b1) -> split into A buffers --------
#pragma unroll
    for (int t = 0; t < 8; t++) {
        int cp0 = warp_n * 64 + t * 8 + lr * 2;
        float2 b1v = __ldg((const float2*)(b1 + cp0));
#pragma unroll
        for (int m = 0; m < 2; m++) {
            int r0 = warp_m * 32 + m * 16 + lq;
            float a0 = s_a[r0], a1 = s_a[r0 + 8];
            float h00 = leaky(a0 * acc1[m * 16 + t][0] + acc1[m * 16 + t + 8][0] + b1v.x);
            float h01 = leaky(a0 * acc1[m * 16 + t][1] + acc1[m * 16 + t + 8][1] + b1v.y);
            float h10 = leaky(a1 * acc1[m * 16 + t][2] + acc1[m * 16 + t + 8][2] + b1v.x);
            float h11 = leaky(a1 * acc1[m * 16 + t][3] + acc1[m * 16 + t + 8][3] + b1v.y);
            uint32_t hi, lo;
            uint32_t s0 = (uint32_t)r0 * A_PITCH_B + (uint32_t)cp0 * 2;
            split2(h00, h01, hi, lo);
            sts32(smA + s0, hi); sts32(smA + A_LO_OFF + s0, lo);
            uint32_t s1 = s0 + 8u * A_PITCH_B;
            split2(h10, h11, hi, lo);
            sts32(smA + s1, hi); sts32(smA + A_LO_OFF + s1, lo);
        }
    }

    // -------- GEMM2: D2(128x128) = H @ W2T --------
    float acc2[16][4];
#pragma unroll
    for (int i = 0; i < 16; i++)
#pragma unroll
        for (int j = 0; j < 4; j++) acc2[i][j] = 0.0f;

    CP_WAIT(1); __syncthreads();                 // W2 chunk0 + H visible
    gemm_chunk<8>(acc2, smA, smB0, warp_m, warp_n, lane);
    CP_WAIT(0); __syncthreads();                 // W2 chunk1 ready
    gemm_chunk<8>(acc2, smA + 128u, smB1, warp_m, warp_n, lane);

    // -------- final epilogue --------
    const float oml = 1.0f - el;
#pragma unroll
    for (int t = 0; t < 8; t++) {
        int cp0 = warp_n * 64 + t * 8 + lr * 2;
        float2 b2v = __ldg((const float2*)(b2 + cp0));
#pragma unroll
        for (int m = 0; m < 2; m++) {
            int r0 = warp_m * 32 + m * 16 + lq;
#pragma unroll
            for (int h = 0; h < 2; h++) {
                int r = r0 + h * 8;
                int node = row0 + r;
                if (node >= n) continue;
                float dsc = s_dsc[r];
                float2 se = *(const float2*)(static_emb + (long)node * DDIM + cp0);
                float o0 = el * se.x + oml * (leaky(acc2[m * 8 + t][2 * h + 0] + b2v.x) * dsc);
                float o1 = el * se.y + oml * (leaky(acc2[m * 8 + t][2 * h + 1] + b2v.y) * dsc);
                *(float2*)(out + (long)node * DDIM + cp0) = make_float2(o0, o1);
            }
        }
    }
}

// ---------------- launch ----------------
extern "C" void kernel_launch(void* const* d_in, const int* in_sizes, int n_in,
                              void* d_out, int out_size) {
    const float* memory      = (const float*)d_in[0];
    const float* last_update = (const float*)d_in[1];
    const float* msgs        = (const float*)d_in[2];
    const float* ts          = (const float*)d_in[3];
    const float* static_emb  = (const float*)d_in[4];
    const float* W1          = (const float*)d_in[5];
    const float* b1          = (const float*)d_in[6];
    const float* W2          = (const float*)d_in[7];
    const float* b2          = (const float*)d_in[8];
    const float* e_lamb      = (const float*)d_in[9];
    const float* now_time    = (const float*)d_in[10];
    const int*   srcs        = (const int*)d_in[11];
    float* out = (float*)d_out;

    const int n = in_sizes[1];
    const int e = in_sizes[3];

    prep_kernel<<<(n + 255) / 256, 256>>>(W1, W2, n);
    scatter_kernel<<<(e + 255) / 256, 256>>>(srcs, e);

    cudaFuncSetAttribute(ctdg_hmma_kernel,
                         cudaFuncAttributeMaxDynamicSharedMemorySize, SMEM_BYTES);
    int grid = (n + TILE_M - 1) / TILE_M;
    ctdg_hmma_kernel<<<grid, NTHR, SMEM_BYTES>>>(
        memory, last_update, msgs, ts, static_emb,
        b1, b2, e_lamb, now_time, out, n);
}

// round 5
// speedup vs baseline: 4.0366x; 1.5909x over previous
#include <cuda_runtime.h>
#include <cuda_bf16.h>
#include <math.h>
#include <stdint.h>

#define NMAX   200000
#define DDIM   128
#define LAMB   30.0f
#define OUTC   30.0f
#define SLOPE  0.01f
#define EPSC   1e-10f

#define TILE_M 64
#define NTHR   256

// A (V/H) smem: 64 rows x 136 bf16 (pitch 272B), hi + lo halves
#define A_PITCH  272u
#define A_LO     17408u
#define A_BYTES  34816

// fragment-major weights: one uint4 per (tile, lane)
// W1: 8 ks x 32 ntiles ; W2: 8 ks x 16 ntiles
__device__ int g_map[NMAX];
__device__ __align__(16) uint4 g_W1f[8 * 32 * 32];
__device__ __align__(16) uint4 g_W2f[8 * 16 * 32];

// ---------------- helpers ----------------
__device__ __forceinline__ uint32_t smem_u32(const void* p) {
    uint32_t a;
    asm("{ .reg .u64 t; cvta.to.shared.u64 t, %1; cvt.u32.u64 %0, t; }" : "=r"(a) : "l"(p));
    return a;
}
__device__ __forceinline__ void sts32(uint32_t a, uint32_t v) {
    asm volatile("st.shared.b32 [%0], %1;" :: "r"(a), "r"(v) : "memory");
}
__device__ __forceinline__ void sts128(uint32_t a, uint32_t x, uint32_t y, uint32_t z, uint32_t w) {
    asm volatile("st.shared.v4.b32 [%0], {%1,%2,%3,%4};" :: "r"(a), "r"(x), "r"(y), "r"(z), "r"(w) : "memory");
}
__device__ __forceinline__ void ldsm4(uint32_t& r0, uint32_t& r1, uint32_t& r2, uint32_t& r3, uint32_t addr) {
    asm volatile("ldmatrix.sync.aligned.m8n8.x4.shared.b16 {%0,%1,%2,%3}, [%4];"
                 : "=r"(r0), "=r"(r1), "=r"(r2), "=r"(r3) : "r"(addr) : "memory");
}
__device__ __forceinline__ void mma16816(float* d,
    uint32_t a0, uint32_t a1, uint32_t a2, uint32_t a3, uint32_t b0, uint32_t b1) {
    asm volatile(
        "mma.sync.aligned.m16n8k16.row.col.f32.bf16.bf16.f32 "
        "{%0,%1,%2,%3}, {%4,%5,%6,%7}, {%8,%9}, {%0,%1,%2,%3};"
        : "+f"(d[0]), "+f"(d[1]), "+f"(d[2]), "+f"(d[3])
        : "r"(a0), "r"(a1), "r"(a2), "r"(a3), "r"(b0), "r"(b1));
}
__device__ __forceinline__ float leaky(float x) { return x >= 0.0f ? x : SLOPE * x; }

__device__ __forceinline__ void split2(float x0, float x1, uint32_t& hi, uint32_t& lo) {
    __nv_bfloat16 h0 = __float2bfloat16(x0), h1 = __float2bfloat16(x1);
    __nv_bfloat16 l0 = __float2bfloat16(x0 - __bfloat162float(h0));
    __nv_bfloat16 l1 = __float2bfloat16(x1 - __bfloat162float(h1));
    hi = (uint32_t)__bfloat16_as_ushort(h0) | ((uint32_t)__bfloat16_as_ushort(h1) << 16);
    lo = (uint32_t)__bfloat16_as_ushort(l0) | ((uint32_t)__bfloat16_as_ushort(l1) << 16);
}
__device__ __forceinline__ void split_store8(uint32_t ahi, uint32_t alo, const float* v) {
    uint32_t hw[4], lw[4];
#pragma unroll
    for (int p = 0; p < 4; p++) split2(v[2 * p], v[2 * p + 1], hw[p], lw[p]);
    sts128(ahi, hw[0], hw[1], hw[2], hw[3]);
    sts128(alo, lw[0], lw[1], lw[2], lw[3]);
}

// ---------------- prep kernels ----------------
// W1T[n][k] (n<128: W1[k][n] "P"; n>=128: W1[128+k][n-128] "Q"), W2T[n][k]=W2[k][n]
// frag u32 slot layout per (tile, lane): {hi(k), hi(k+8), lo(k), lo(k+8)}
__global__ void prep_kernel(const float* __restrict__ W1, const float* __restrict__ W2, int n) {
    int i = blockIdx.x * blockDim.x + threadIdx.x;
    if (i < n) g_map[i] = -1;
    if (i < 32768) {     // W1 frags: 8*32 tiles * 32 lanes * 4 slots u32
        int slot = i & 3, lane = (i >> 2) & 31, tile = i >> 7;
        int ks = tile >> 5, t = tile & 31;
        int nn = t * 8 + (lane >> 2);
        int k  = ks * 16 + (slot & 1) * 8 + (lane & 3) * 2;
        float v0 = (nn < 128) ? W1[k * DDIM + nn]       : W1[(128 + k) * DDIM + (nn - 128)];
        float v1 = (nn < 128) ? W1[(k + 1) * DDIM + nn] : W1[(129 + k) * DDIM + (nn - 128)];
        uint32_t hi, lo; split2(v0, v1, hi, lo);
        ((uint32_t*)g_W1f)[i] = (slot < 2) ? hi : lo;
    }
    if (i < 16384) {     // W2 frags: 8*16 tiles
        int slot = i & 3, lane = (i >> 2) & 31, tile = i >> 7;
        int ks = tile >> 4, t = tile & 15;
        int nn = t * 8 + (lane >> 2);
        int k  = ks * 16 + (slot & 1) * 8 + (lane & 3) * 2;
        float v0 = W2[k * DDIM + nn];
        float v1 = W2[(k + 1) * DDIM + nn];
        uint32_t hi, lo; split2(v0, v1, hi, lo);
        ((uint32_t*)g_W2f)[i] = (slot < 2) ? hi : lo;
    }
}
__global__ void scatter_kernel(const int* __restrict__ srcs, int e) {
    int i = blockIdx.x * blockDim.x + threadIdx.x;
    if (i < e) g_map[srcs[i]] = i;
}

// ---------------- main kernel ----------------
__global__ __launch_bounds__(NTHR, 2)
void ctdg_hmma_kernel(
    const float* __restrict__ memory,
    const float* __restrict__ last_update,
    const float* __restrict__ msgs,
    const float* __restrict__ ts,
    const float* __restrict__ static_emb,
    const float* __restrict__ b1,
    const float* __restrict__ b2,
    const float* __restrict__ e_lamb_p,
    const float* __restrict__ now_p,
    float* __restrict__ out,
    int n)
{
    __shared__ __align__(16) char sAraw[A_BYTES];
    __shared__ float s_dec[TILE_M], s_a[TILE_M], s_dsc[TILE_M];
    __shared__ int   s_e[TILE_M];

    const int tid = threadIdx.x;
    const int wid = tid >> 5;
    const int lane = tid & 31;
    const int lq = lane >> 2, lr = lane & 3;
    const int l8 = lane & 7, q = lane >> 3;
    const int warp_m = wid & 1;        // 2 M-slices of 32 rows
    const int warp_n = wid >> 1;       // 4 N-slices
    const int row0 = blockIdx.x * TILE_M;

    const uint32_t smA = smem_u32(sAraw);

    const float now = __ldg(now_p);
    const float el  = __ldg(e_lamb_p);

    // ---- per-row params ----
    if (tid < TILE_M) {
        int node = row0 + tid;
        float dec = 1.0f, lu = 0.0f, cnt = 1.0f;
        int e = -1;
        if (node < n) {
            e = g_map[node];
            float lun = last_update[node];
            float cm  = memory[(long)node * (DDIM + 1) + DDIM];
            if (e >= 0) {
                lu  = ts[e];
                dec = expf((lun - lu) * (1.0f / LAMB));
                cnt = cm * dec + msgs[(long)e * (DDIM + 1) + DDIM];
            } else { lu = lun; cnt = cm; }
        }
        s_dec[tid] = dec; s_e[tid] = e;
        s_a[tid]   = 1.0f / (cnt + EPSC);
        s_dsc[tid] = expf((lu - now) * (1.0f / OUTC));
    }
    __syncthreads();

    // ---- build V = mem*dec + msg (64x128) split hi/lo into A smem ----
    for (int g = tid; g < TILE_M * 16; g += NTHR) {
        int r = g >> 4, k0 = (g & 15) * 8;
        int node = row0 + r;
        float v[8];
        if (node < n) {
            float dec = s_dec[r];
            int e = s_e[r];
            const float* mrow = memory + (long)node * (DDIM + 1) + k0;
#pragma unroll
            for (int j = 0; j < 8; j++) v[j] = mrow[j] * dec;
            if (e >= 0) {
                const float* gm = msgs + (long)e * (DDIM + 1) + k0;
#pragma unroll
                for (int j = 0; j < 8; j++) v[j] += gm[j];
            }
        } else {
#pragma unroll
            for (int j = 0; j < 8; j++) v[j] = 0.0f;
        }
        uint32_t soff = (uint32_t)r * A_PITCH + (uint32_t)k0 * 2;
        split_store8(smA + soff, smA + A_LO + soff, v);
    }
    __syncthreads();

    // ---- GEMM1: [P|Q](64x256) = V @ W1T, 3-term split, B frags via LDG.128 ----
    // acc1[m*8 + t]: t 0..3 = P cols warp_n*32+t*8 ; t 4..7 = Q (same cols + 128)
    float acc1[16][4];
#pragma unroll
    for (int i = 0; i < 16; i++)
#pragma unroll
        for (int j = 0; j < 4; j++) acc1[i][j] = 0.0f;

#pragma unroll
    for (int ks = 0; ks < 8; ks++) {
        const uint32_t koff = (uint32_t)ks * 32u;
        uint32_t ah[2][4], al[2][4];
#pragma unroll
        for (int m = 0; m < 2; m++) {
            uint32_t rowa = (uint32_t)(warp_m * 32 + m * 16 + (q & 1) * 8 + l8);
            uint32_t aoff = rowa * A_PITCH + koff + (uint32_t)(q >> 1) * 16u;
            ldsm4(ah[m][0], ah[m][1], ah[m][2], ah[m][3], smA + aoff);
            ldsm4(al[m][0], al[m][1], al[m][2], al[m][3], smA + A_LO + aoff);
        }
#pragma unroll
        for (int t = 0; t < 8; t++) {
            int tg = (t < 4) ? (warp_n * 4 + t) : (16 + warp_n * 4 + (t - 4));
            uint4 bv = __ldg(&g_W1f[(ks * 32 + tg) * 32 + lane]);
#pragma unroll
            for (int m = 0; m < 2; m++) {
                mma16816(acc1[m * 8 + t], ah[m][0], ah[m][1], ah[m][2], ah[m][3], bv.x, bv.y);
                mma16816(acc1[m * 8 + t], ah[m][0], ah[m][1], ah[m][2], ah[m][3], bv.z, bv.w);
                mma16816(acc1[m * 8 + t], al[m][0], al[m][1], al[m][2], al[m][3], bv.x, bv.y);
            }
        }
    }
    __syncthreads();   // all warps done reading V

    // ---- mid epilogue: H = leaky(a*P + Q + b1) -> split into A smem ----
#pragma unroll
    for (int t = 0; t < 4; t++) {
        int cp0 = warp_n * 32 + t * 8 + lr * 2;
        float2 b1v = __ldg((const float2*)(b1 + cp0));
#pragma unroll
        for (int m = 0; m < 2; m++) {
            int r0 = warp_m * 32 + m * 16 + lq;
            float a0 = s_a[r0], a1 = s_a[r0 + 8];
            float h00 = leaky(a0 * acc1[m * 8 + t][0] + acc1[m * 8 + t + 4][0] + b1v.x);
            float h01 = leaky(a0 * acc1[m * 8 + t][1] + acc1[m * 8 + t + 4][1] + b1v.y);
            float h10 = leaky(a1 * acc1[m * 8 + t][2] + acc1[m * 8 + t + 4][2] + b1v.x);
            float h11 = leaky(a1 * acc1[m * 8 + t][3] + acc1[m * 8 + t + 4][3] + b1v.y);
            uint32_t hi, lo;
            uint32_t s0 = (uint32_t)r0 * A_PITCH + (uint32_t)cp0 * 2;
            split2(h00, h01, hi, lo);
            sts32(smA + s0, hi); sts32(smA + A_LO + s0, lo);
            uint32_t s1 = s0 + 8u * A_PITCH;
            split2(h10, h11, hi, lo);
            sts32(smA + s1, hi); sts32(smA + A_LO + s1, lo);
        }
    }
    __syncthreads();   // H visible to all warps

    // ---- GEMM2: D2(64x128) = H @ W2T ----
    float acc2[8][4];
#pragma unroll
    for (int i = 0; i < 8; i++)
#pragma unroll
        for (int j = 0; j < 4; j++) acc2[i][j] = 0.0f;

#pragma unroll
    for (int ks = 0; ks < 8; ks++) {
        const uint32_t koff = (uint32_t)ks * 32u;
        uint32_t ah[2][4], al[2][4];
#pragma unroll
        for (int m = 0; m < 2; m++) {
            uint32_t rowa = (uint32_t)(warp_m * 32 + m * 16 + (q & 1) * 8 + l8);
            uint32_t aoff = rowa * A_PITCH + koff + (uint32_t)(q >> 1) * 16u;
            ldsm4(ah[m][0], ah[m][1], ah[m][2], ah[m][3], smA + aoff);
            ldsm4(al[m][0], al[m][1], al[m][2], al[m][3], smA + A_LO + aoff);
        }
#pragma unroll
        for (int t = 0; t < 4; t++) {
            int tg = warp_n * 4 + t;
            uint4 bv = __ldg(&g_W2f[(ks * 16 + tg) * 32 + lane]);
#pragma unroll
            for (int m = 0; m < 2; m++) {
                mma16816(acc2[m * 4 + t], ah[m][0], ah[m][1], ah[m][2], ah[m][3], bv.x, bv.y);
                mma16816(acc2[m * 4 + t], ah[m][0], ah[m][1], ah[m][2], ah[m][3], bv.z, bv.w);
                mma16816(acc2[m * 4 + t], al[m][0], al[m][1], al[m][2], al[m][3], bv.x, bv.y);
            }
        }
    }

    // ---- final epilogue ----
    const float oml = 1.0f - el;
#pragma unroll
    for (int t = 0; t < 4; t++) {
        int cp0 = warp_n * 32 + t * 8 + lr * 2;
        float2 b2v = __ldg((const float2*)(b2 + cp0));
#pragma unroll
        for (int m = 0; m < 2; m++) {
            int r0 = warp_m * 32 + m * 16 + lq;
#pragma unroll
            for (int h = 0; h < 2; h++) {
                int r = r0 + h * 8;
                int node = row0 + r;
                if (node >= n) continue;
                float dsc = s_dsc[r];
                float2 se = *(const float2*)(static_emb + (long)node * DDIM + cp0);
                float o0 = el * se.x + oml * (leaky(acc2[m * 4 + t][2 * h + 0] + b2v.x) * dsc);
                float o1 = el * se.y + oml * (leaky(acc2[m * 4 + t][2 * h + 1] + b2v.y) * dsc);
                *(float2*)(out + (long)node * DDIM + cp0) = make_float2(o0, o1);
            }
        }
    }
}

// ---------------- launch ----------------
extern "C" void kernel_launch(void* const* d_in, const int* in_sizes, int n_in,
                              void* d_out, int out_size) {
    const float* memory      = (const float*)d_in[0];
    const float* last_update = (const float*)d_in[1];
    const float* msgs        = (const float*)d_in[2];
    const float* ts          = (const float*)d_in[3];
    const float* static_emb  = (const float*)d_in[4];
    const float* W1          = (const float*)d_in[5];
    const float* b1          = (const float*)d_in[6];
    const float* W2          = (const float*)d_in[7];
    const float* b2          = (const float*)d_in[8];
    const float* e_lamb      = (const float*)d_in[9];
    const float* now_time    = (const float*)d_in[10];
    const int*   srcs        = (const int*)d_in[11];
    float* out = (float*)d_out;

    const int n = in_sizes[1];
    const int e = in_sizes[3];

    prep_kernel<<<(n + 255) / 256, 256>>>(W1, W2, n);
    scatter_kernel<<<(e + 255) / 256, 256>>>(srcs, e);

    int grid = (n + TILE_M - 1) / TILE_M;
    ctdg_hmma_kernel<<<grid, NTHR>>>(
        memory, last_update, msgs, ts, static_emb,
        b1, b2, e_lamb, now_time, out, n);
}

// round 6
// speedup vs baseline: 4.7275x; 1.1712x over previous
#include <cuda_runtime.h>
#include <cuda_fp16.h>
#include <math.h>
#include <stdint.h>

#define NMAX   200000
#define DDIM   128
#define LAMB   30.0f
#define OUTC   30.0f
#define SLOPE  0.01f
#define EPSC   1e-10f

#define TILE_M 64
#define NTHR   256

// A (V/H) smem: 64 rows x 136 fp16 (pitch 272B), single precision level (no lo)
#define A_PITCH  272u
#define A_BYTES  17408

// fragment-major weights (fp16 hi/lo packed): one uint4 per (tile, lane)
// slots: {hi(k..k+7), hi(k+8..k+15), lo(k..k+7), lo(k+8..k+15)}
__device__ int g_map[NMAX];
__device__ __align__(16) uint4 g_W1f[8 * 32 * 32];
__device__ __align__(16) uint4 g_W2f[8 * 16 * 32];

// ---------------- helpers ----------------
__device__ __forceinline__ uint32_t smem_u32(const void* p) {
    uint32_t a;
    asm("{ .reg .u64 t; cvta.to.shared.u64 t, %1; cvt.u32.u64 %0, t; }" : "=r"(a) : "l"(p));
    return a;
}
__device__ __forceinline__ void sts32(uint32_t a, uint32_t v) {
    asm volatile("st.shared.b32 [%0], %1;" :: "r"(a), "r"(v) : "memory");
}
__device__ __forceinline__ void sts128(uint32_t a, uint32_t x, uint32_t y, uint32_t z, uint32_t w) {
    asm volatile("st.shared.v4.b32 [%0], {%1,%2,%3,%4};" :: "r"(a), "r"(x), "r"(y), "r"(z), "r"(w) : "memory");
}
__device__ __forceinline__ void ldsm4(uint32_t& r0, uint32_t& r1, uint32_t& r2, uint32_t& r3, uint32_t addr) {
    asm volatile("ldmatrix.sync.aligned.m8n8.x4.shared.b16 {%0,%1,%2,%3}, [%4];"
                 : "=r"(r0), "=r"(r1), "=r"(r2), "=r"(r3) : "r"(addr) : "memory");
}
__device__ __forceinline__ void mma16816(float* d,
    uint32_t a0, uint32_t a1, uint32_t a2, uint32_t a3, uint32_t b0, uint32_t b1) {
    asm volatile(
        "mma.sync.aligned.m16n8k16.row.col.f32.f16.f16.f32 "
        "{%0,%1,%2,%3}, {%4,%5,%6,%7}, {%8,%9}, {%0,%1,%2,%3};"
        : "+f"(d[0]), "+f"(d[1]), "+f"(d[2]), "+f"(d[3])
        : "r"(a0), "r"(a1), "r"(a2), "r"(a3), "r"(b0), "r"(b1));
}
__device__ __forceinline__ float leaky(float x) { return x >= 0.0f ? x : SLOPE * x; }

// pack two floats as fp16x2 (round-nearest)
__device__ __forceinline__ uint32_t pack2h(float x0, float x1) {
    __half2 h = __floats2half2_rn(x0, x1);
    return *(uint32_t*)&h;
}
// fp16 split: hi + lo (exact residual capture)
__device__ __forceinline__ void split2h(float x0, float x1, uint32_t& hi, uint32_t& lo) {
    __half h0 = __float2half_rn(x0), h1 = __float2half_rn(x1);
    __half l0 = __float2half_rn(x0 - __half2float(h0));
    __half l1 = __float2half_rn(x1 - __half2float(h1));
    hi = (uint32_t)__half_as_ushort(h0) | ((uint32_t)__half_as_ushort(h1) << 16);
    lo = (uint32_t)__half_as_ushort(l0) | ((uint32_t)__half_as_ushort(l1) << 16);
}
__device__ __forceinline__ void store8h(uint32_t addr, const float* v) {
    sts128(addr, pack2h(v[0], v[1]), pack2h(v[2], v[3]), pack2h(v[4], v[5]), pack2h(v[6], v[7]));
}

// ---------------- prep kernels ----------------
// W1T[n][k] (n<128: W1[k][n] "P"; n>=128: W1[128+k][n-128] "Q"), W2T[n][k]=W2[k][n]
__global__ void prep_kernel(const float* __restrict__ W1, const float* __restrict__ W2, int n) {
    int i = blockIdx.x * blockDim.x + threadIdx.x;
    if (i < n) g_map[i] = -1;
    if (i < 32768) {     // W1 frags: 8*32 tiles * 32 lanes * 4 slots u32
        int slot = i & 3, lane = (i >> 2) & 31, tile = i >> 7;
        int ks = tile >> 5, t = tile & 31;
        int nn = t * 8 + (lane >> 2);
        int k  = ks * 16 + (slot & 1) * 8 + (lane & 3) * 2;
        float v0 = (nn < 128) ? W1[k * DDIM + nn]       : W1[(128 + k) * DDIM + (nn - 128)];
        float v1 = (nn < 128) ? W1[(k + 1) * DDIM + nn] : W1[(129 + k) * DDIM + (nn - 128)];
        uint32_t hi, lo; split2h(v0, v1, hi, lo);
        ((uint32_t*)g_W1f)[i] = (slot < 2) ? hi : lo;
    }
    if (i < 16384) {     // W2 frags: 8*16 tiles
        int slot = i & 3, lane = (i >> 2) & 31, tile = i >> 7;
        int ks = tile >> 4, t = tile & 15;
        int nn = t * 8 + (lane >> 2);
        int k  = ks * 16 + (slot & 1) * 8 + (lane & 3) * 2;
        float v0 = W2[k * DDIM + nn];
        float v1 = W2[(k + 1) * DDIM + nn];
        uint32_t hi, lo; split2h(v0, v1, hi, lo);
        ((uint32_t*)g_W2f)[i] = (slot < 2) ? hi : lo;
    }
}
__global__ void scatter_kernel(const int* __restrict__ srcs, int e) {
    int i = blockIdx.x * blockDim.x + threadIdx.x;
    if (i < e) g_map[srcs[i]] = i;
}

// ---------------- main kernel ----------------
__global__ __launch_bounds__(NTHR, 2)
void ctdg_hmma_kernel(
    const float* __restrict__ memory,
    const float* __restrict__ last_update,
    const float* __restrict__ msgs,
    const float* __restrict__ ts,
    const float* __restrict__ static_emb,
    const float* __restrict__ b1,
    const float* __restrict__ b2,
    const float* __restrict__ e_lamb_p,
    const float* __restrict__ now_p,
    float* __restrict__ out,
    int n)
{
    __shared__ __align__(16) char sAraw[A_BYTES];
    __shared__ float s_dec[TILE_M], s_a[TILE_M], s_dsc[TILE_M];
    __shared__ int   s_e[TILE_M];

    const int tid = threadIdx.x;
    const int wid = tid >> 5;
    const int lane = tid & 31;
    const int lq = lane >> 2, lr = lane & 3;
    const int l8 = lane & 7, q = lane >> 3;
    const int warp_m = wid & 1;        // 2 M-slices of 32 rows
    const int warp_n = wid >> 1;       // 4 N-slices
    const int row0 = blockIdx.x * TILE_M;

    const uint32_t smA = smem_u32(sAraw);

    const float now = __ldg(now_p);
    const float el  = __ldg(e_lamb_p);

    // ---- per-row params ----
    if (tid < TILE_M) {
        int node = row0 + tid;
        float dec = 1.0f, lu = 0.0f, cnt = 1.0f;
        int e = -1;
        if (node < n) {
            e = g_map[node];
            float lun = last_update[node];
            float cm  = memory[(long)node * (DDIM + 1) + DDIM];
            if (e >= 0) {
                lu  = ts[e];
                dec = expf((lun - lu) * (1.0f / LAMB));
                cnt = cm * dec + msgs[(long)e * (DDIM + 1) + DDIM];
            } else { lu = lun; cnt = cm; }
        }
        s_dec[tid] = dec; s_e[tid] = e;
        s_a[tid]   = 1.0f / (cnt + EPSC);
        s_dsc[tid] = expf((lu - now) * (1.0f / OUTC));
    }
    __syncthreads();

    // ---- build V = mem*dec + msg (64x128), fp16 into A smem ----
    for (int g = tid; g < TILE_M * 16; g += NTHR) {
        int r = g >> 4, k0 = (g & 15) * 8;
        int node = row0 + r;
        float v[8];
        if (node < n) {
            float dec = s_dec[r];
            int e = s_e[r];
            const float* mrow = memory + (long)node * (DDIM + 1) + k0;
#pragma unroll
            for (int j = 0; j < 8; j++) v[j] = mrow[j] * dec;
            if (e >= 0) {
                const float* gm = msgs + (long)e * (DDIM + 1) + k0;
#pragma unroll
                for (int j = 0; j < 8; j++) v[j] += gm[j];
            }
        } else {
#pragma unroll
            for (int j = 0; j < 8; j++) v[j] = 0.0f;
        }
        store8h(smA + (uint32_t)r * A_PITCH + (uint32_t)k0 * 2, v);
    }
    __syncthreads();

    // ---- GEMM1: [P|Q](64x256) = V @ W1T, A single fp16, B 2-term ----
    float acc1[16][4];
#pragma unroll
    for (int i = 0; i < 16; i++)
#pragma unroll
        for (int j = 0; j < 4; j++) acc1[i][j] = 0.0f;

#pragma unroll
    for (int ks = 0; ks < 8; ks++) {
        const uint32_t koff = (uint32_t)ks * 32u;
        uint32_t ah[2][4];
#pragma unroll
        for (int m = 0; m < 2; m++) {
            uint32_t rowa = (uint32_t)(warp_m * 32 + m * 16 + (q & 1) * 8 + l8);
            uint32_t aoff = rowa * A_PITCH + koff + (uint32_t)(q >> 1) * 16u;
            ldsm4(ah[m][0], ah[m][1], ah[m][2], ah[m][3], smA + aoff);
        }
#pragma unroll
        for (int t = 0; t < 8; t++) {
            int tg = (t < 4) ? (warp_n * 4 + t) : (16 + warp_n * 4 + (t - 4));
            uint4 bv = __ldg(&g_W1f[(ks * 32 + tg) * 32 + lane]);
#pragma unroll
            for (int m = 0; m < 2; m++) {
                mma16816(acc1[m * 8 + t], ah[m][0], ah[m][1], ah[m][2], ah[m][3], bv.x, bv.y);
                mma16816(acc1[m * 8 + t], ah[m][0], ah[m][1], ah[m][2], ah[m][3], bv.z, bv.w);
            }
        }
    }
    __syncthreads();   // all warps done reading V

    // ---- mid epilogue: H = leaky(a*P + Q + b1) -> fp16 into A smem ----
#pragma unroll
    for (int t = 0; t < 4; t++) {
        int cp0 = warp_n * 32 + t * 8 + lr * 2;
        float2 b1v = __ldg((const float2*)(b1 + cp0));
#pragma unroll
        for (int m = 0; m < 2; m++) {
            int r0 = warp_m * 32 + m * 16 + lq;
            float a0 = s_a[r0], a1 = s_a[r0 + 8];
            float h00 = leaky(a0 * acc1[m * 8 + t][0] + acc1[m * 8 + t + 4][0] + b1v.x);
            float h01 = leaky(a0 * acc1[m * 8 + t][1] + acc1[m * 8 + t + 4][1] + b1v.y);
            float h10 = leaky(a1 * acc1[m * 8 + t][2] + acc1[m * 8 + t + 4][2] + b1v.x);
            float h11 = leaky(a1 * acc1[m * 8 + t][3] + acc1[m * 8 + t + 4][3] + b1v.y);
            uint32_t s0 = (uint32_t)r0 * A_PITCH + (uint32_t)cp0 * 2;
            sts32(smA + s0, pack2h(h00, h01));
            sts32(smA + s0 + 8u * A_PITCH, pack2h(h10, h11));
        }
    }
    __syncthreads();   // H visible to all warps

    // ---- GEMM2: D2(64x128) = H @ W2T ----
    float acc2[8][4];
#pragma unroll
    for (int i = 0; i < 8; i++)
#pragma unroll
        for (int j = 0; j < 4; j++) acc2[i][j] = 0.0f;

#pragma unroll
    for (int ks = 0; ks < 8; ks++) {
        const uint32_t koff = (uint32_t)ks * 32u;
        uint32_t ah[2][4];
#pragma unroll
        for (int m = 0; m < 2; m++) {
            uint32_t rowa = (uint32_t)(warp_m * 32 + m * 16 + (q & 1) * 8 + l8);
            uint32_t aoff = rowa * A_PITCH + koff + (uint32_t)(q >> 1) * 16u;
            ldsm4(ah[m][0], ah[m][1], ah[m][2], ah[m][3], smA + aoff);
        }
#pragma unroll
        for (int t = 0; t < 4; t++) {
            int tg = warp_n * 4 + t;
            uint4 bv = __ldg(&g_W2f[(ks * 16 + tg) * 32 + lane]);
#pragma unroll
            for (int m = 0; m < 2; m++) {
                mma16816(acc2[m * 4 + t], ah[m][0], ah[m][1], ah[m][2], ah[m][3], bv.x, bv.y);
                mma16816(acc2[m * 4 + t], ah[m][0], ah[m][1], ah[m][2], ah[m][3], bv.z, bv.w);
            }
        }
    }

    // ---- final epilogue ----
    const float oml = 1.0f - el;
#pragma unroll
    for (int t = 0; t < 4; t++) {
        int cp0 = warp_n * 32 + t * 8 + lr * 2;
        float2 b2v = __ldg((const float2*)(b2 + cp0));
#pragma unroll
        for (int m = 0; m < 2; m++) {
            int r0 = warp_m * 32 + m * 16 + lq;
#pragma unroll
            for (int h = 0; h < 2; h++) {
                int r = r0 + h * 8;
                int node = row0 + r;
                if (node >= n) continue;
                float dsc = s_dsc[r];
                float2 se = *(const float2*)(static_emb + (long)node * DDIM + cp0);
                float o0 = el * se.x + oml * (leaky(acc2[m * 4 + t][2 * h + 0] + b2v.x) * dsc);
                float o1 = el * se.y + oml * (leaky(acc2[m * 4 + t][2 * h + 1] + b2v.y) * dsc);
                *(float2*)(out + (long)node * DDIM + cp0) = make_float2(o0, o1);
            }
        }
    }
}

// ---------------- launch ----------------
extern "C" void kernel_launch(void* const* d_in, const int* in_sizes, int n_in,
                              void* d_out, int out_size) {
    const float* memory      = (const float*)d_in[0];
    const float* last_update = (const float*)d_in[1];
    const float* msgs        = (const float*)d_in[2];
    const float* ts          = (const float*)d_in[3];
    const float* static_emb  = (const float*)d_in[4];
    const float* W1          = (const float*)d_in[5];
    const float* b1          = (const float*)d_in[6];
    const float* W2          = (const float*)d_in[7];
    const float* b2          = (const float*)d_in[8];
    const float* e_lamb      = (const float*)d_in[9];
    const float* now_time    = (const float*)d_in[10];
    const int*   srcs        = (const int*)d_in[11];
    float* out = (float*)d_out;

    const int n = in_sizes[1];
    const int e = in_sizes[3];

    prep_kernel<<<(n + 255) / 256, 256>>>(W1, W2, n);
    scatter_kernel<<<(e + 255) / 256, 256>>>(srcs, e);

    int grid = (n + TILE_M - 1) / TILE_M;
    ctdg_hmma_kernel<<<grid, NTHR>>>(
        memory, last_update, msgs, ts, static_emb,
        b1, b2, e_lamb, now_time, out, n);
}

// round 7
// speedup vs baseline: 5.4199x; 1.1464x over previous
#include <cuda_runtime.h>
#include <cuda_fp16.h>
#include <math.h>
#include <stdint.h>

#define NMAX   200000
#define DDIM   128
#define LAMB   30.0f
#define OUTC   30.0f
#define SLOPE  0.01f
#define EPSC   1e-10f

#define TILE_M 64
#define NTHR   256

// A (V/H) smem: 64 rows x 136 fp16 (pitch 272B)
#define A_PITCH  272u
#define A_BYTES  17408

// fragment-major weights (single fp16): one uint2 per (tile, lane)
// slots: {k..k+7, k+8..k+15}
__device__ int g_map[NMAX];
__device__ __align__(16) uint2 g_W1f[8 * 32 * 32];
__device__ __align__(16) uint2 g_W2f[8 * 16 * 32];

// ---------------- helpers ----------------
__device__ __forceinline__ uint32_t smem_u32(const void* p) {
    uint32_t a;
    asm("{ .reg .u64 t; cvta.to.shared.u64 t, %1; cvt.u32.u64 %0, t; }" : "=r"(a) : "l"(p));
    return a;
}
__device__ __forceinline__ void sts32(uint32_t a, uint32_t v) {
    asm volatile("st.shared.b32 [%0], %1;" :: "r"(a), "r"(v) : "memory");
}
__device__ __forceinline__ void sts128(uint32_t a, uint32_t x, uint32_t y, uint32_t z, uint32_t w) {
    asm volatile("st.shared.v4.b32 [%0], {%1,%2,%3,%4};" :: "r"(a), "r"(x), "r"(y), "r"(z), "r"(w) : "memory");
}
__device__ __forceinline__ void ldsm4(uint32_t& r0, uint32_t& r1, uint32_t& r2, uint32_t& r3, uint32_t addr) {
    asm volatile("ldmatrix.sync.aligned.m8n8.x4.shared.b16 {%0,%1,%2,%3}, [%4];"
                 : "=r"(r0), "=r"(r1), "=r"(r2), "=r"(r3) : "r"(addr) : "memory");
}
__device__ __forceinline__ void mma16816(float* d,
    uint32_t a0, uint32_t a1, uint32_t a2, uint32_t a3, uint32_t b0, uint32_t b1) {
    asm volatile(
        "mma.sync.aligned.m16n8k16.row.col.f32.f16.f16.f32 "
        "{%0,%1,%2,%3}, {%4,%5,%6,%7}, {%8,%9}, {%0,%1,%2,%3};"
        : "+f"(d[0]), "+f"(d[1]), "+f"(d[2]), "+f"(d[3])
        : "r"(a0), "r"(a1), "r"(a2), "r"(a3), "r"(b0), "r"(b1));
}
__device__ __forceinline__ float leaky(float x) { return x >= 0.0f ? x : SLOPE * x; }

__device__ __forceinline__ uint32_t pack2h(float x0, float x1) {
    __half2 h = __floats2half2_rn(x0, x1);
    return *(uint32_t*)&h;
}
__device__ __forceinline__ void store8h(uint32_t addr, const float* v) {
    sts128(addr, pack2h(v[0], v[1]), pack2h(v[2], v[3]), pack2h(v[4], v[5]), pack2h(v[6], v[7]));
}

// ---------------- prep kernels ----------------
// W1T[n][k] (n<128: W1[k][n] "P"; n>=128: W1[128+k][n-128] "Q"), W2T[n][k]=W2[k][n]
__global__ void prep_kernel(const float* __restrict__ W1, const float* __restrict__ W2, int n) {
    int i = blockIdx.x * blockDim.x + threadIdx.x;
    if (i < n) g_map[i] = -1;
    if (i < 16384) {     // W1 frags: 8*32 tiles * 32 lanes * 2 slots u32
        int slot = i & 1, lane = (i >> 1) & 31, tile = i >> 6;
        int ks = tile >> 5, t = tile & 31;
        int nn = t * 8 + (lane >> 2);
        int k  = ks * 16 + slot * 8 + (lane & 3) * 2;
        float v0 = (nn < 128) ? W1[k * DDIM + nn]       : W1[(128 + k) * DDIM + (nn - 128)];
        float v1 = (nn < 128) ? W1[(k + 1) * DDIM + nn] : W1[(129 + k) * DDIM + (nn - 128)];
        ((uint32_t*)g_W1f)[i] = pack2h(v0, v1);
    }
    if (i < 8192) {      // W2 frags: 8*16 tiles
        int slot = i & 1, lane = (i >> 1) & 31, tile = i >> 6;
        int ks = tile >> 4, t = tile & 15;
        int nn = t * 8 + (lane >> 2);
        int k  = ks * 16 + slot * 8 + (lane & 3) * 2;
        ((uint32_t*)g_W2f)[i] = pack2h(W2[k * DDIM + nn], W2[(k + 1) * DDIM + nn]);
    }
}
__global__ void scatter_kernel(const int* __restrict__ srcs, int e) {
    int i = blockIdx.x * blockDim.x + threadIdx.x;
    if (i < e) g_map[srcs[i]] = i;
}

// ---------------- main kernel ----------------
__global__ __launch_bounds__(NTHR, 2)
void ctdg_hmma_kernel(
    const float* __restrict__ memory,
    const float* __restrict__ last_update,
    const float* __restrict__ msgs,
    const float* __restrict__ ts,
    const float* __restrict__ static_emb,
    const float* __restrict__ b1,
    const float* __restrict__ b2,
    const float* __restrict__ e_lamb_p,
    const float* __restrict__ now_p,
    float* __restrict__ out,
    int n)
{
    __shared__ __align__(16) char sAraw[A_BYTES];
    __shared__ float s_dec[TILE_M], s_a[TILE_M], s_dsc[TILE_M];
    __shared__ int   s_e[TILE_M];

    const int tid = threadIdx.x;
    const int wid = tid >> 5;
    const int lane = tid & 31;
    const int lq = lane >> 2, lr = lane & 3;
    const int l8 = lane & 7, q = lane >> 3;
    const int warp_m = wid & 1;        // 2 M-slices of 32 rows
    const int warp_n = wid >> 1;       // 4 N-slices
    const int row0 = blockIdx.x * TILE_M;

    const uint32_t smA = smem_u32(sAraw);

    const float now = __ldg(now_p);
    const float el  = __ldg(e_lamb_p);

    // ---- per-row params ----
    if (tid < TILE_M) {
        int node = row0 + tid;
        float dec = 1.0f, lu = 0.0f, cnt = 1.0f;
        int e = -1;
        if (node < n) {
            e = g_map[node];
            float lun = last_update[node];
            float cm  = memory[(long)node * (DDIM + 1) + DDIM];
            if (e >= 0) {
                lu  = ts[e];
                dec = expf((lun - lu) * (1.0f / LAMB));
                cnt = cm * dec + msgs[(long)e * (DDIM + 1) + DDIM];
            } else { lu = lun; cnt = cm; }
        }
        s_dec[tid] = dec; s_e[tid] = e;
        s_a[tid]   = 1.0f / (cnt + EPSC);
        s_dsc[tid] = expf((lu - now) * (1.0f / OUTC));
    }
    __syncthreads();

    // ---- build V = mem*dec + msg (64x128), fp16 into A smem ----
    for (int g = tid; g < TILE_M * 16; g += NTHR) {
        int r = g >> 4, k0 = (g & 15) * 8;
        int node = row0 + r;
        float v[8];
        if (node < n) {
            float dec = s_dec[r];
            int e = s_e[r];
            const float* mrow = memory + (long)node * (DDIM + 1) + k0;
#pragma unroll
            for (int j = 0; j < 8; j++) v[j] = mrow[j] * dec;
            if (e >= 0) {
                const float* gm = msgs + (long)e * (DDIM + 1) + k0;
#pragma unroll
                for (int j = 0; j < 8; j++) v[j] += gm[j];
            }
        } else {
#pragma unroll
            for (int j = 0; j < 8; j++) v[j] = 0.0f;
        }
        store8h(smA + (uint32_t)r * A_PITCH + (uint32_t)k0 * 2, v);
    }
    __syncthreads();

    // ---- GEMM1: [P|Q](64x256) = V @ W1T ----
    float acc1[16][4];
#pragma unroll
    for (int i = 0; i < 16; i++)
#pragma unroll
        for (int j = 0; j < 4; j++) acc1[i][j] = 0.0f;

#pragma unroll
    for (int ks = 0; ks < 8; ks++) {
        const uint32_t koff = (uint32_t)ks * 32u;
        uint32_t ah[2][4];
#pragma unroll
        for (int m = 0; m < 2; m++) {
            uint32_t rowa = (uint32_t)(warp_m * 32 + m * 16 + (q & 1) * 8 + l8);
            uint32_t aoff = rowa * A_PITCH + koff + (uint32_t)(q >> 1) * 16u;
            ldsm4(ah[m][0], ah[m][1], ah[m][2], ah[m][3], smA + aoff);
        }
#pragma unroll
        for (int t = 0; t < 8; t++) {
            int tg = (t < 4) ? (warp_n * 4 + t) : (16 + warp_n * 4 + (t - 4));
            uint2 bv = __ldg(&g_W1f[(ks * 32 + tg) * 32 + lane]);
#pragma unroll
            for (int m = 0; m < 2; m++)
                mma16816(acc1[m * 8 + t], ah[m][0], ah[m][1], ah[m][2], ah[m][3], bv.x, bv.y);
        }
    }
    __syncthreads();   // all warps done reading V

    // ---- mid epilogue: H = leaky(a*P + Q + b1) -> fp16 into A smem ----
#pragma unroll
    for (int t = 0; t < 4; t++) {
        int cp0 = warp_n * 32 + t * 8 + lr * 2;
        float2 b1v = __ldg((const float2*)(b1 + cp0));
#pragma unroll
        for (int m = 0; m < 2; m++) {
            int r0 = warp_m * 32 + m * 16 + lq;
            float a0 = s_a[r0], a1 = s_a[r0 + 8];
            float h00 = leaky(a0 * acc1[m * 8 + t][0] + acc1[m * 8 + t + 4][0] + b1v.x);
            float h01 = leaky(a0 * acc1[m * 8 + t][1] + acc1[m * 8 + t + 4][1] + b1v.y);
            float h10 = leaky(a1 * acc1[m * 8 + t][2] + acc1[m * 8 + t + 4][2] + b1v.x);
            float h11 = leaky(a1 * acc1[m * 8 + t][3] + acc1[m * 8 + t + 4][3] + b1v.y);
            uint32_t s0 = (uint32_t)r0 * A_PITCH + (uint32_t)cp0 * 2;
            sts32(smA + s0, pack2h(h00, h01));
            sts32(smA + s0 + 8u * A_PITCH, pack2h(h10, h11));
        }
    }
    __syncthreads();   // H visible to all warps

    // ---- GEMM2: D2(64x128) = H @ W2T ----
    float acc2[8][4];
#pragma unroll
    for (int i = 0; i < 8; i++)
#pragma unroll
        for (int j = 0; j < 4; j++) acc2[i][j] = 0.0f;

#pragma unroll
    for (int ks = 0; ks < 8; ks++) {
        const uint32_t koff = (uint32_t)ks * 32u;
        uint32_t ah[2][4];
#pragma unroll
        for (int m = 0; m < 2; m++) {
            uint32_t rowa = (uint32_t)(warp_m * 32 + m * 16 + (q & 1) * 8 + l8);
            uint32_t aoff = rowa * A_PITCH + koff + (uint32_t)(q >> 1) * 16u;
            ldsm4(ah[m][0], ah[m][1], ah[m][2], ah[m][3], smA + aoff);
        }
#pragma unroll
        for (int t = 0; t < 4; t++) {
            int tg = warp_n * 4 + t;
            uint2 bv = __ldg(&g_W2f[(ks * 16 + tg) * 32 + lane]);
#pragma unroll
            for (int m = 0; m < 2; m++)
                mma16816(acc2[m * 4 + t], ah[m][0], ah[m][1], ah[m][2], ah[m][3], bv.x, bv.y);
        }
    }

    // ---- final epilogue ----
    const float oml = 1.0f - el;
#pragma unroll
    for (int t = 0; t < 4; t++) {
        int cp0 = warp_n * 32 + t * 8 + lr * 2;
        float2 b2v = __ldg((const float2*)(b2 + cp0));
#pragma unroll
        for (int m = 0; m < 2; m++) {
            int r0 = warp_m * 32 + m * 16 + lq;
#pragma unroll
            for (int h = 0; h < 2; h++) {
                int r = r0 + h * 8;
                int node = row0 + r;
                if (node >= n) continue;
                float dsc = s_dsc[r];
                float2 se = *(const float2*)(static_emb + (long)node * DDIM + cp0);
                float o0 = el * se.x + oml * (leaky(acc2[m * 4 + t][2 * h + 0] + b2v.x) * dsc);
                float o1 = el * se.y + oml * (leaky(acc2[m * 4 + t][2 * h + 1] + b2v.y) * dsc);
                *(float2*)(out + (long)node * DDIM + cp0) = make_float2(o0, o1);
            }
        }
    }
}

// ---------------- launch ----------------
extern "C" void kernel_launch(void* const* d_in, const int* in_sizes, int n_in,
                              void* d_out, int out_size) {
    const float* memory      = (const float*)d_in[0];
    const float* last_update = (const float*)d_in[1];
    const float* msgs        = (const float*)d_in[2];
    const float* ts          = (const float*)d_in[3];
    const float* static_emb  = (const float*)d_in[4];
    const float* W1          = (const float*)d_in[5];
    const float* b1          = (const float*)d_in[6];
    const float* W2          = (const float*)d_in[7];
    const float* b2          = (const float*)d_in[8];
    const float* e_lamb      = (const float*)d_in[9];
    const float* now_time    = (const float*)d_in[10];
    const int*   srcs        = (const int*)d_in[11];
    float* out = (float*)d_out;

    const int n = in_sizes[1];
    const int e = in_sizes[3];

    prep_kernel<<<(n + 255) / 256, 256>>>(W1, W2, n);
    scatter_kernel<<<(e + 255) / 256, 256>>>(srcs, e);

    int grid = (n + TILE_M - 1) / TILE_M;
    ctdg_hmma_kernel<<<grid, NTHR>>>(
        memory, last_update, msgs, ts, static_emb,
        b1, b2, e_lamb, now_time, out, n);
}